// round 14
// baseline (speedup 1.0000x reference)
#include <cuda_runtime.h>
#include <cstdint>

#define KS     5
#define K2     25
#define DYN    32
#define NB     4
#define NC     64
#define NH     256
#define NW     256
#define HW     (NH*NW)

#define TW     32
#define TH     8
#define PW     4
#define SW     36                 // tile cols w0 .. w0+35 (origin w0, 16B aligned)
#define SH     12                 // rows h0-2 .. h0+9
#define CHK    4                  // channels per chunk
#define F4_CH  (SH*(SW/4))        // 108 float4 per channel
#define F4_CK  (CHK*F4_CH)        // 432 float4 per chunk
#define NSLOT  7                  // ceil(432/64)
#define NTHR   64
#define NCHUNK 16                 // 8 static + 8 dynamic
#define BUFS   3

#define SMEM_BYTES (BUFS*F4_CK*16 + NSLOT*NTHR*4 + K2*4)

__device__ __forceinline__ void cp_async16(uint32_t saddr, const float* gaddr, unsigned sz)
{
    asm volatile("cp.async.cg.shared.global [%0], [%1], 16, %2;\n"
                 :: "r"(saddr), "l"(gaddr), "r"(sz) : "memory");
}
__device__ __forceinline__ void cp_commit()
{
    asm volatile("cp.async.commit_group;\n" ::: "memory");
}
__device__ __forceinline__ float2 ffma2(float2 a, float2 b, float2 c)
{
    unsigned long long ua = *reinterpret_cast<unsigned long long*>(&a);
    unsigned long long ub = *reinterpret_cast<unsigned long long*>(&b);
    unsigned long long uc = *reinterpret_cast<unsigned long long*>(&c);
    unsigned long long ud;
    asm("fma.rn.f32x2 %0, %1, %2, %3;" : "=l"(ud) : "l"(ua), "l"(ub), "l"(uc));
    return *reinterpret_cast<float2*>(&ud);
}

// one strip row: 10 FFMA2 covering 25 tap-MACs for 4 pixels (paired (0,1),(2,3))
__device__ __forceinline__ void row_macs(const float* rp, float2 v01, float2 v23,
                                         float2* s01, float2* s23)
{
    const float4 A = *(const float4*)(rp);
    const float4 B = *(const float4*)(rp + 4);
    const float2 q0 = make_float2(A.x, A.y);
    const float2 q1 = make_float2(A.y, A.z);
    const float2 q2 = make_float2(A.z, A.w);
    const float2 q3 = make_float2(A.w, B.x);
    const float2 q4 = make_float2(B.x, B.y);
    const float2 q5 = make_float2(B.y, B.z);
    const float2 q6 = make_float2(B.z, B.w);
    s01[0] = ffma2(q0, v01, s01[0]);
    s01[1] = ffma2(q1, v01, s01[1]);
    s01[2] = ffma2(q2, v01, s01[2]);
    s01[3] = ffma2(q3, v01, s01[3]);
    s01[4] = ffma2(q4, v01, s01[4]);
    s23[0] = ffma2(q2, v23, s23[0]);
    s23[1] = ffma2(q3, v23, s23[1]);
    s23[2] = ffma2(q4, v23, s23[2]);
    s23[3] = ffma2(q5, v23, s23[3]);
    s23[4] = ffma2(q6, v23, s23[4]);
}
__device__ __forceinline__ void row_wsum(const float* rp, const float2* w01, const float2* w23,
                                         float2& a01, float2& a23)
{
    const float4 A = *(const float4*)(rp);
    const float4 B = *(const float4*)(rp + 4);
    const float2 q0 = make_float2(A.x, A.y);
    const float2 q1 = make_float2(A.y, A.z);
    const float2 q2 = make_float2(A.z, A.w);
    const float2 q3 = make_float2(A.w, B.x);
    const float2 q4 = make_float2(B.x, B.y);
    const float2 q5 = make_float2(B.y, B.z);
    const float2 q6 = make_float2(B.z, B.w);
    a01 = ffma2(w01[0], q0, a01);
    a01 = ffma2(w01[1], q1, a01);
    a01 = ffma2(w01[2], q2, a01);
    a01 = ffma2(w01[3], q3, a01);
    a01 = ffma2(w01[4], q4, a01);
    a23 = ffma2(w23[0], q2, a23);
    a23 = ffma2(w23[1], q3, a23);
    a23 = ffma2(w23[2], q4, a23);
    a23 = ffma2(w23[3], q5, a23);
    a23 = ffma2(w23[4], q6, a23);
}

__global__ __launch_bounds__(NTHR, 8)
void la_kernel(const float* __restrict__ x,
               const float* __restrict__ kern,
               float* __restrict__ out)
{
    // ===================== EDGE BLOCKS (by == 32): pixels col 0,1 =====================
    if (blockIdx.y == 32) {
        const int tid = threadIdx.x;
        const int b   = blockIdx.z;
        const int R   = blockIdx.x * 32 + (tid >> 1);   // row 0..255
        const int col = tid & 1;                         // 0 or 1
        const float* xb = x + (long)b * NC * HW;

        float sc[K2];
        #pragma unroll
        for (int k = 0; k < K2; ++k) sc[k] = 0.0f;

        for (int ch = DYN; ch < NC; ++ch) {
            const float* cp = xb + ch * HW;
            float4 rowv[KS];
            #pragma unroll
            for (int i = 0; i < KS; ++i) {
                const int gr = R - 2 + i;
                rowv[i] = ((unsigned)gr < NH) ? *(const float4*)(cp + gr * NW)
                                              : make_float4(0.f, 0.f, 0.f, 0.f);
            }
            const float v = (col == 0) ? rowv[2].x : rowv[2].y;
            #pragma unroll
            for (int i = 0; i < KS; ++i) {
                if (col == 0) {
                    sc[i * KS + 2] = fmaf(rowv[i].x, v, sc[i * KS + 2]);
                    sc[i * KS + 3] = fmaf(rowv[i].y, v, sc[i * KS + 3]);
                    sc[i * KS + 4] = fmaf(rowv[i].z, v, sc[i * KS + 4]);
                } else {
                    sc[i * KS + 1] = fmaf(rowv[i].x, v, sc[i * KS + 1]);
                    sc[i * KS + 2] = fmaf(rowv[i].y, v, sc[i * KS + 2]);
                    sc[i * KS + 3] = fmaf(rowv[i].z, v, sc[i * KS + 3]);
                    sc[i * KS + 4] = fmaf(rowv[i].w, v, sc[i * KS + 4]);
                }
            }
        }
        {
            float tmp[K2];
            #pragma unroll
            for (int k = 0; k < K2; ++k) tmp[k] = sc[k] * (__ldg(kern + k) * 0.2f);
            float m2 = tmp[0];
            #pragma unroll
            for (int k = 1; k < K2; ++k) m2 = fmaxf(m2, tmp[k]);
            float sum = 0.0f;
            #pragma unroll
            for (int k = 0; k < K2; ++k) { tmp[k] = __expf(tmp[k] - m2); sum += tmp[k]; }
            const float inv = 1.0f / sum;
            #pragma unroll
            for (int k = 0; k < K2; ++k) sc[k] = tmp[k] * inv;
        }
        for (int ch = 0; ch < DYN; ++ch) {
            const float* cp = xb + ch * HW;
            float acc = 0.0f;
            #pragma unroll
            for (int i = 0; i < KS; ++i) {
                const int gr = R - 2 + i;
                const float4 rv = ((unsigned)gr < NH) ? *(const float4*)(cp + gr * NW)
                                                      : make_float4(0.f, 0.f, 0.f, 0.f);
                if (col == 0) {
                    acc = fmaf(sc[i * KS + 2], rv.x, acc);
                    acc = fmaf(sc[i * KS + 3], rv.y, acc);
                    acc = fmaf(sc[i * KS + 4], rv.z, acc);
                } else {
                    acc = fmaf(sc[i * KS + 1], rv.x, acc);
                    acc = fmaf(sc[i * KS + 2], rv.y, acc);
                    acc = fmaf(sc[i * KS + 3], rv.z, acc);
                    acc = fmaf(sc[i * KS + 4], rv.w, acc);
                }
            }
            out[((long)(b * DYN + ch) * NH + R) * NW + col] = acc;
        }
        return;
    }

    // ===================== MAIN BLOCKS =====================
    extern __shared__ __align__(16) unsigned char dynsm[];
    float4* smbuf = (float4*)dynsm;                             // [BUFS][F4_CK]
    int*    sgoff = (int*)(dynsm + (size_t)BUFS * F4_CK * 16);  // [NSLOT][NTHR]
    float*  skw   = (float*)(sgoff + NSLOT * NTHR);             // [K2]

    const int tid = threadIdx.x;
    const int tx  = tid & 7;                  // 0..7
    const int ty  = tid >> 3;                 // 0..7
    const int w0  = blockIdx.x * TW;
    const int h0  = blockIdx.y * TH;
    const int b   = blockIdx.z;
    const int ph  = h0 + ty;
    const int p0  = w0 + 2 + tx * PW;         // first owned pixel (shifted by +2)

    if (tid < K2) skw[tid] = kern[tid] * (1.4426950408889634f / KS);

    #pragma unroll
    for (int s = 0; s < NSLOT; ++s) {
        const int e   = tid + s * NTHR;
        const int ch  = e / F4_CH;
        const int rem = e - ch * F4_CH;
        const int r   = rem / (SW / 4);
        const int j   = rem - r * (SW / 4);
        const int gh  = h0 - 2 + r;
        const int gw0 = w0 + j * 4;
        const bool ok = ((unsigned)gh < NH) && ((unsigned)gw0 < NW);
        sgoff[s * NTHR + tid] = ok ? (ch * HW + gh * NW + gw0) : -1;
    }

    const float* xb = x + (long)b * NC * HW;

    // ---- prologue: issue chunks 0, 1 ----
    #pragma unroll
    for (int pre = 0; pre < 2; ++pre) {
        const float* g = xb + (32 + 4 * pre) * HW;
        const uint32_t sb = (uint32_t)__cvta_generic_to_shared(&smbuf[(size_t)pre * F4_CK]);
        #pragma unroll
        for (int s = 0; s < NSLOT; ++s) {
            const int e = tid + s * NTHR;
            if (s < NSLOT - 1 || e < F4_CK) {
                const int off = sgoff[s * NTHR + tid];
                cp_async16(sb + (uint32_t)e * 16u, g + (off >= 0 ? off : 0),
                           off >= 0 ? 16u : 0u);
            }
        }
        cp_commit();
    }

    // paired scores: sc01[k] = {score(px0,k), score(px1,k)}, sc23 likewise
    float2 sc01[K2], sc23[K2];
    #pragma unroll
    for (int k = 0; k < K2; ++k) {
        sc01[k] = make_float2(0.f, 0.f);
        sc23[k] = make_float2(0.f, 0.f);
    }

    float inv[PW];

    for (int i = 0; i < NCHUNK; ++i) {
        // 1) wait: chunk i resident (per-thread groups; outstanding = {i, i+1})
        if (i < NCHUNK - 1) {
            asm volatile("cp.async.wait_group 1;\n" ::: "memory");
        } else {
            asm volatile("cp.async.wait_group 0;\n" ::: "memory");
        }
        // 2) barrier: (a) all threads' chunk-i data visible;
        //    (b) all warps finished compute i-1  => buffer (i+2)%3 reusable
        __syncthreads();
        // 3) issue chunk i+2 into buffer (i+2)%3 — race-free by (b)
        if (i + 2 < NCHUNK) {
            const int cn = i + 2;
            const int cb = (cn < 8) ? (32 + 4 * cn) : (4 * (cn - 8));
            const float* g = xb + cb * HW;
            const uint32_t sb = (uint32_t)__cvta_generic_to_shared(
                &smbuf[(size_t)(cn % BUFS) * F4_CK]);
            #pragma unroll
            for (int s = 0; s < NSLOT; ++s) {
                const int e = tid + s * NTHR;
                if (s < NSLOT - 1 || e < F4_CK) {
                    const int off = sgoff[s * NTHR + tid];
                    cp_async16(sb + (uint32_t)e * 16u, g + (off >= 0 ? off : 0),
                               off >= 0 ? 16u : 0u);
                }
            }
            cp_commit();
        }

        const float* buf = (const float*)&smbuf[(size_t)(i % BUFS) * F4_CK];

        if (i < 8) {
            // ================= Phase A: scores (FFMA2) =================
            #pragma unroll
            for (int cc = 0; cc < CHK; ++cc) {
                const float* chb = buf + cc * (SH * SW) + ty * SW + tx * 4;
                float2 v01, v23;
                {   // row r=2: center pairs are aligned halves of the strip
                    const float4 A = *(const float4*)(chb + 2 * SW);
                    const float4 B = *(const float4*)(chb + 2 * SW + 4);
                    v01 = make_float2(A.z, A.w);
                    v23 = make_float2(B.x, B.y);
                }
                row_macs(chb + 2 * SW, v01, v23, sc01 + 10, sc23 + 10);
                row_macs(chb + 0 * SW, v01, v23, sc01 + 0,  sc23 + 0);
                row_macs(chb + 1 * SW, v01, v23, sc01 + 5,  sc23 + 5);
                row_macs(chb + 3 * SW, v01, v23, sc01 + 15, sc23 + 15);
                row_macs(chb + 4 * SW, v01, v23, sc01 + 20, sc23 + 20);
            }
            if (i == 7) {
                // ================= Phase B: softmax (log2 domain) =================
                #pragma unroll
                for (int k = 0; k < K2; ++k) {
                    const float kw = skw[k];
                    sc01[k].x *= kw; sc01[k].y *= kw;
                    sc23[k].x *= kw; sc23[k].y *= kw;
                }
                float mx[PW] = {sc01[0].x, sc01[0].y, sc23[0].x, sc23[0].y};
                #pragma unroll
                for (int k = 1; k < K2; ++k) {
                    mx[0] = fmaxf(mx[0], sc01[k].x);
                    mx[1] = fmaxf(mx[1], sc01[k].y);
                    mx[2] = fmaxf(mx[2], sc23[k].x);
                    mx[3] = fmaxf(mx[3], sc23[k].y);
                }
                float sum[PW] = {0.f, 0.f, 0.f, 0.f};
                #pragma unroll
                for (int k = 0; k < K2; ++k) {
                    sc01[k].x = exp2f(sc01[k].x - mx[0]); sum[0] += sc01[k].x;
                    sc01[k].y = exp2f(sc01[k].y - mx[1]); sum[1] += sc01[k].y;
                    sc23[k].x = exp2f(sc23[k].x - mx[2]); sum[2] += sc23[k].x;
                    sc23[k].y = exp2f(sc23[k].y - mx[3]); sum[3] += sc23[k].y;
                }
                #pragma unroll
                for (int p = 0; p < PW; ++p) inv[p] = 1.0f / sum[p];
            }
        } else {
            // ================= Phase C: weighted sum (FFMA2) =================
            #pragma unroll
            for (int cc = 0; cc < CHK; ++cc) {
                const float* chb = buf + cc * (SH * SW) + ty * SW + tx * 4;
                float2 a01 = make_float2(0.f, 0.f);
                float2 a23 = make_float2(0.f, 0.f);
                row_wsum(chb + 0 * SW, sc01 + 0,  sc23 + 0,  a01, a23);
                row_wsum(chb + 1 * SW, sc01 + 5,  sc23 + 5,  a01, a23);
                row_wsum(chb + 2 * SW, sc01 + 10, sc23 + 10, a01, a23);
                row_wsum(chb + 3 * SW, sc01 + 15, sc23 + 15, a01, a23);
                row_wsum(chb + 4 * SW, sc01 + 20, sc23 + 20, a01, a23);

                const int c = (i - 8) * CHK + cc;
                float* op = &out[(((long)b * DYN + c) * NH + ph) * NW + p0];
                float2 o0 = make_float2(a01.x * inv[0], a01.y * inv[1]);
                *(float2*)op = o0;                       // pixels p0, p0+1
                if (p0 + 2 < NW) {                        // masked for last block, tx=7
                    float2 o1 = make_float2(a23.x * inv[2], a23.y * inv[3]);
                    *(float2*)(op + 2) = o1;
                }
            }
        }
    }
}

extern "C" void kernel_launch(void* const* d_in, const int* in_sizes, int n_in,
                              void* d_out, int out_size)
{
    const float* x    = (const float*)d_in[0];
    const float* kern = (const float*)d_in[1];
    float* out        = (float*)d_out;
    (void)in_sizes; (void)n_in; (void)out_size;

    static bool attr_set = false;
    if (!attr_set) {
        cudaFuncSetAttribute(la_kernel, cudaFuncAttributeMaxDynamicSharedMemorySize,
                             SMEM_BYTES);
        attr_set = true;
    }

    dim3 grid(NW / TW, NH / TH + 1, NB);   // (8, 33, 4): by==32 -> edge blocks
    dim3 block(NTHR);
    la_kernel<<<grid, block, SMEM_BYTES>>>(x, kern, out);
}

// round 15
// speedup vs baseline: 1.0369x; 1.0369x over previous
#include <cuda_runtime.h>
#include <cstdint>

#define KS     5
#define K2     25
#define DYN    32
#define NB     4
#define NC     64
#define NH     256
#define NW     256
#define HW     (NH*NW)

#define TW     32
#define TH     8
#define PW     4
#define SW     36                 // tile cols w0 .. w0+35 (origin w0, 16B aligned)
#define SH     12                 // rows h0-2 .. h0+9
#define CHK    4                  // channels per chunk
#define F4_CH  (SH*(SW/4))        // 108 float4 per channel
#define F4_CK  (CHK*F4_CH)        // 432 float4 per chunk (live data)
#define NSLOT  7                  // fill slots per thread
#define F4_BUF (NSLOT*NTHR)       // 448 float4 per buffer (padded, predicate-free fill)
#define NTHR   64
#define NCHUNK 16                 // 8 static + 8 dynamic
#define BUFS   3

#define SMEM_BYTES (BUFS*F4_BUF*16 + NSLOT*NTHR*4 + K2*4)

__device__ __forceinline__ void cp_async16(uint32_t saddr, const float* gaddr, unsigned sz)
{
    asm volatile("cp.async.cg.shared.global [%0], [%1], 16, %2;\n"
                 :: "r"(saddr), "l"(gaddr), "r"(sz) : "memory");
}
__device__ __forceinline__ void cp_commit()
{
    asm volatile("cp.async.commit_group;\n" ::: "memory");
}

__global__ __launch_bounds__(NTHR, 8)
void la_kernel(const float* __restrict__ x,
               const float* __restrict__ kern,
               float* __restrict__ out)
{
    // ===================== EDGE BLOCKS (by == 32): pixels col 0,1 =====================
    if (blockIdx.y == 32) {
        const int tid = threadIdx.x;
        const int b   = blockIdx.z;
        const int R   = blockIdx.x * 32 + (tid >> 1);   // row 0..255
        const int col = tid & 1;                         // 0 or 1
        const float* xb = x + (long)b * NC * HW;

        float sc[K2];
        #pragma unroll
        for (int k = 0; k < K2; ++k) sc[k] = 0.0f;

        for (int ch = DYN; ch < NC; ++ch) {
            const float* cp = xb + ch * HW;
            float4 rowv[KS];
            #pragma unroll
            for (int i = 0; i < KS; ++i) {
                const int gr = R - 2 + i;
                rowv[i] = ((unsigned)gr < NH) ? *(const float4*)(cp + gr * NW)
                                              : make_float4(0.f, 0.f, 0.f, 0.f);
            }
            const float v = (col == 0) ? rowv[2].x : rowv[2].y;
            #pragma unroll
            for (int i = 0; i < KS; ++i) {
                if (col == 0) {
                    sc[i * KS + 2] = fmaf(rowv[i].x, v, sc[i * KS + 2]);
                    sc[i * KS + 3] = fmaf(rowv[i].y, v, sc[i * KS + 3]);
                    sc[i * KS + 4] = fmaf(rowv[i].z, v, sc[i * KS + 4]);
                } else {
                    sc[i * KS + 1] = fmaf(rowv[i].x, v, sc[i * KS + 1]);
                    sc[i * KS + 2] = fmaf(rowv[i].y, v, sc[i * KS + 2]);
                    sc[i * KS + 3] = fmaf(rowv[i].z, v, sc[i * KS + 3]);
                    sc[i * KS + 4] = fmaf(rowv[i].w, v, sc[i * KS + 4]);
                }
            }
        }
        {
            float tmp[K2];
            #pragma unroll
            for (int k = 0; k < K2; ++k) tmp[k] = sc[k] * (__ldg(kern + k) * 0.2f);
            float m2 = tmp[0];
            #pragma unroll
            for (int k = 1; k < K2; ++k) m2 = fmaxf(m2, tmp[k]);
            float sum = 0.0f;
            #pragma unroll
            for (int k = 0; k < K2; ++k) { tmp[k] = __expf(tmp[k] - m2); sum += tmp[k]; }
            const float inv = 1.0f / sum;
            #pragma unroll
            for (int k = 0; k < K2; ++k) sc[k] = tmp[k] * inv;
        }
        for (int ch = 0; ch < DYN; ++ch) {
            const float* cp = xb + ch * HW;
            float acc = 0.0f;
            #pragma unroll
            for (int i = 0; i < KS; ++i) {
                const int gr = R - 2 + i;
                const float4 rv = ((unsigned)gr < NH) ? *(const float4*)(cp + gr * NW)
                                                      : make_float4(0.f, 0.f, 0.f, 0.f);
                if (col == 0) {
                    acc = fmaf(sc[i * KS + 2], rv.x, acc);
                    acc = fmaf(sc[i * KS + 3], rv.y, acc);
                    acc = fmaf(sc[i * KS + 4], rv.z, acc);
                } else {
                    acc = fmaf(sc[i * KS + 1], rv.x, acc);
                    acc = fmaf(sc[i * KS + 2], rv.y, acc);
                    acc = fmaf(sc[i * KS + 3], rv.z, acc);
                    acc = fmaf(sc[i * KS + 4], rv.w, acc);
                }
            }
            out[((long)(b * DYN + ch) * NH + R) * NW + col] = acc;
        }
        return;
    }

    // ===================== MAIN BLOCKS =====================
    extern __shared__ __align__(16) unsigned char dynsm[];
    float4* smbuf = (float4*)dynsm;                             // [BUFS][F4_BUF]
    int*    sgoff = (int*)(dynsm + (size_t)BUFS * F4_BUF * 16); // [NSLOT][NTHR]
    float*  skw   = (float*)(sgoff + NSLOT * NTHR);             // [K2]

    const int tid = threadIdx.x;
    const int tx  = tid & 7;                  // 0..7
    const int ty  = tid >> 3;                 // 0..7
    const int w0  = blockIdx.x * TW;
    const int h0  = blockIdx.y * TH;
    const int b   = blockIdx.z;
    const int ph  = h0 + ty;
    const int p0  = w0 + 2 + tx * PW;         // first owned pixel (shifted by +2)

    // fold log2(e)/KS into tap weights -> exp2f softmax
    if (tid < K2) skw[tid] = kern[tid] * (1.4426950408889634f / KS);

    // ---- chunk-invariant fill descriptors; each thread reads only its own rows ----
    #pragma unroll
    for (int s = 0; s < NSLOT; ++s) {
        const int e   = tid + s * NTHR;
        const int ch  = e / F4_CH;
        const int rem = e - ch * F4_CH;
        const int r   = rem / (SW / 4);
        const int j   = rem - r * (SW / 4);
        const int gh  = h0 - 2 + r;
        const int gw0 = w0 + j * 4;
        // slots with e >= F4_CK land in buffer padding (zero-fill, never read)
        const bool ok = (e < F4_CK) && ((unsigned)gh < NH) && ((unsigned)gw0 < NW);
        sgoff[s * NTHR + tid] = ok ? (ch * HW + gh * NW + gw0) : -1;
    }

    const float* xb = x + (long)b * NC * HW;

    // ---- prologue: issue chunks 0, 1 ----
    #pragma unroll
    for (int pre = 0; pre < 2; ++pre) {
        const float* g = xb + (32 + 4 * pre) * HW;
        const uint32_t sb = (uint32_t)__cvta_generic_to_shared(&smbuf[(size_t)pre * F4_BUF]);
        #pragma unroll
        for (int s = 0; s < NSLOT; ++s) {
            const int e = tid + s * NTHR;
            const int off = sgoff[s * NTHR + tid];
            cp_async16(sb + (uint32_t)e * 16u, g + (off >= 0 ? off : 0),
                       off >= 0 ? 16u : 0u);
        }
        cp_commit();
    }

    float sc[PW][K2];
    #pragma unroll
    for (int p = 0; p < PW; ++p)
        #pragma unroll
        for (int k = 0; k < K2; ++k) sc[p][k] = 0.0f;

    float inv[PW];

    for (int i = 0; i < NCHUNK; ++i) {
        // 1) wait: chunk i resident (outstanding groups = {i, i+1})
        if (i < NCHUNK - 1) {
            asm volatile("cp.async.wait_group 1;\n" ::: "memory");
        } else {
            asm volatile("cp.async.wait_group 0;\n" ::: "memory");
        }
        // 2) barrier: (a) chunk-i data visible to all; (b) all warps done with
        //    compute i-1 => buffer (i+2)%3 is reusable. Race-free by construction.
        __syncthreads();
        // 3) issue chunk i+2 into buffer (i+2)%3
        if (i + 2 < NCHUNK) {
            const int cn = i + 2;
            const int cb = (cn < 8) ? (32 + 4 * cn) : (4 * (cn - 8));
            const float* g = xb + cb * HW;
            const uint32_t sb = (uint32_t)__cvta_generic_to_shared(
                &smbuf[(size_t)(cn % BUFS) * F4_BUF]);
            #pragma unroll
            for (int s = 0; s < NSLOT; ++s) {
                const int e = tid + s * NTHR;
                const int off = sgoff[s * NTHR + tid];
                cp_async16(sb + (uint32_t)e * 16u, g + (off >= 0 ? off : 0),
                           off >= 0 ? 16u : 0u);
            }
            cp_commit();
        }

        const float* buf = (const float*)&smbuf[(size_t)(i % BUFS) * F4_BUF];

        if (i < 8) {
            // ================= Phase A: scores (scalar FFMA) =================
            #pragma unroll
            for (int cc = 0; cc < CHK; ++cc) {
                const float* chb = buf + cc * (SH * SW) + ty * SW + tx * 4;
                float v[PW];
                {   // row r=2: strip supplies taps AND the 4 center values
                    const float4 A = *(const float4*)(chb + 2 * SW);
                    const float4 B = *(const float4*)(chb + 2 * SW + 4);
                    v[0] = A.z; v[1] = A.w; v[2] = B.x; v[3] = B.y;
                    const float s[8] = {A.x, A.y, A.z, A.w, B.x, B.y, B.z, B.w};
                    #pragma unroll
                    for (int j = 0; j < KS; ++j)
                        #pragma unroll
                        for (int p = 0; p < PW; ++p)
                            sc[p][10 + j] = fmaf(s[j + p], v[p], sc[p][10 + j]);
                }
                #pragma unroll
                for (int rr = 0; rr < 4; ++rr) {
                    const int r = (rr < 2) ? rr : rr + 1;   // 0,1,3,4
                    const float4 A = *(const float4*)(chb + r * SW);
                    const float4 B = *(const float4*)(chb + r * SW + 4);
                    const float s[8] = {A.x, A.y, A.z, A.w, B.x, B.y, B.z, B.w};
                    #pragma unroll
                    for (int j = 0; j < KS; ++j)
                        #pragma unroll
                        for (int p = 0; p < PW; ++p)
                            sc[p][r * KS + j] = fmaf(s[j + p], v[p], sc[p][r * KS + j]);
                }
            }
            if (i == 7) {
                // ================= Phase B: softmax (log2 domain) =================
                #pragma unroll
                for (int k = 0; k < K2; ++k) {
                    const float kw = skw[k];
                    #pragma unroll
                    for (int p = 0; p < PW; ++p) sc[p][k] *= kw;
                }
                #pragma unroll
                for (int p = 0; p < PW; ++p) {
                    float mx = sc[p][0];
                    #pragma unroll
                    for (int k = 1; k < K2; ++k) mx = fmaxf(mx, sc[p][k]);
                    float sum = 0.0f;
                    #pragma unroll
                    for (int k = 0; k < K2; ++k) {
                        const float e = exp2f(sc[p][k] - mx);
                        sc[p][k] = e;
                        sum += e;
                    }
                    inv[p] = 1.0f / sum;
                }
            }
        } else {
            // ================= Phase C: weighted sum (scalar FFMA) =================
            #pragma unroll
            for (int cc = 0; cc < CHK; ++cc) {
                const float* chb = buf + cc * (SH * SW) + ty * SW + tx * 4;
                float acc[PW] = {0.f, 0.f, 0.f, 0.f};
                #pragma unroll
                for (int r = 0; r < KS; ++r) {
                    const float4 A = *(const float4*)(chb + r * SW);
                    const float4 B = *(const float4*)(chb + r * SW + 4);
                    const float s[8] = {A.x, A.y, A.z, A.w, B.x, B.y, B.z, B.w};
                    #pragma unroll
                    for (int j = 0; j < KS; ++j)
                        #pragma unroll
                        for (int p = 0; p < PW; ++p)
                            acc[p] = fmaf(sc[p][r * KS + j], s[j + p], acc[p]);
                }
                const int c = (i - 8) * CHK + cc;
                float* op = &out[(((long)b * DYN + c) * NH + ph) * NW + p0];
                float2 o0 = make_float2(acc[0] * inv[0], acc[1] * inv[1]);
                *(float2*)op = o0;                       // pixels p0, p0+1
                if (p0 + 2 < NW) {                        // masked for last block, tx=7
                    float2 o1 = make_float2(acc[2] * inv[2], acc[3] * inv[3]);
                    *(float2*)(op + 2) = o1;
                }
            }
        }
    }
}

extern "C" void kernel_launch(void* const* d_in, const int* in_sizes, int n_in,
                              void* d_out, int out_size)
{
    const float* x    = (const float*)d_in[0];
    const float* kern = (const float*)d_in[1];
    float* out        = (float*)d_out;
    (void)in_sizes; (void)n_in; (void)out_size;

    static bool attr_set = false;
    if (!attr_set) {
        cudaFuncSetAttribute(la_kernel, cudaFuncAttributeMaxDynamicSharedMemorySize,
                             SMEM_BYTES);
        attr_set = true;
    }

    dim3 grid(NW / TW, NH / TH + 1, NB);   // (8, 33, 4): by==32 -> edge blocks
    dim3 block(NTHR);
    la_kernel<<<grid, block, SMEM_BYTES>>>(x, kern, out);
}

// round 16
// speedup vs baseline: 1.3017x; 1.2554x over previous
#include <cuda_runtime.h>
#include <cstdint>

#define KS     5
#define K2     25
#define DYN    32
#define NB     4
#define NC     64
#define NH     256
#define NW     256
#define HW     (NH*NW)

#define TW     32
#define TH     8
#define PW     4
#define SW     36                 // tile cols w0 .. w0+35 (origin w0, 16B aligned)
#define SH     12                 // rows h0-2 .. h0+9
#define CHK    2                  // channels per chunk
#define F4_CH  (SH*(SW/4))        // 108 float4 per channel
#define F4_CK  (CHK*F4_CH)        // 216 float4 per chunk
#define NSLOT  4                  // ceil(216/64)
#define NTHR   64
#define NCHUNK 32                 // 16 static + 16 dynamic
#define BUFS   6                  // prefetch distance 4, issue-before-wait safe
#define DIST   4

#define SMEM_BYTES (BUFS*F4_CK*16 + NSLOT*NTHR*4 + K2*4)

__device__ __forceinline__ void cp_async16(uint32_t saddr, const float* gaddr, unsigned sz)
{
    asm volatile("cp.async.cg.shared.global [%0], [%1], 16, %2;\n"
                 :: "r"(saddr), "l"(gaddr), "r"(sz) : "memory");
}
__device__ __forceinline__ void cp_commit()
{
    asm volatile("cp.async.commit_group;\n" ::: "memory");
}

__global__ __launch_bounds__(NTHR, 8)
void la_kernel(const float* __restrict__ x,
               const float* __restrict__ kern,
               float* __restrict__ out)
{
    // ===================== EDGE BLOCKS (by == 32): pixels col 0,1 =====================
    if (blockIdx.y == 32) {
        const int tid = threadIdx.x;
        const int b   = blockIdx.z;
        const int R   = blockIdx.x * 32 + (tid >> 1);   // row 0..255
        const int col = tid & 1;                         // 0 or 1
        const float* xb = x + (long)b * NC * HW;

        float sc[K2];
        #pragma unroll
        for (int k = 0; k < K2; ++k) sc[k] = 0.0f;

        for (int ch = DYN; ch < NC; ++ch) {
            const float* cp = xb + ch * HW;
            float4 rowv[KS];
            #pragma unroll
            for (int i = 0; i < KS; ++i) {
                const int gr = R - 2 + i;
                rowv[i] = ((unsigned)gr < NH) ? *(const float4*)(cp + gr * NW)
                                              : make_float4(0.f, 0.f, 0.f, 0.f);
            }
            const float v = (col == 0) ? rowv[2].x : rowv[2].y;
            #pragma unroll
            for (int i = 0; i < KS; ++i) {
                if (col == 0) {
                    sc[i * KS + 2] = fmaf(rowv[i].x, v, sc[i * KS + 2]);
                    sc[i * KS + 3] = fmaf(rowv[i].y, v, sc[i * KS + 3]);
                    sc[i * KS + 4] = fmaf(rowv[i].z, v, sc[i * KS + 4]);
                } else {
                    sc[i * KS + 1] = fmaf(rowv[i].x, v, sc[i * KS + 1]);
                    sc[i * KS + 2] = fmaf(rowv[i].y, v, sc[i * KS + 2]);
                    sc[i * KS + 3] = fmaf(rowv[i].z, v, sc[i * KS + 3]);
                    sc[i * KS + 4] = fmaf(rowv[i].w, v, sc[i * KS + 4]);
                }
            }
        }
        {
            float tmp[K2];
            #pragma unroll
            for (int k = 0; k < K2; ++k) tmp[k] = sc[k] * (__ldg(kern + k) * 0.2f);
            float m2 = tmp[0];
            #pragma unroll
            for (int k = 1; k < K2; ++k) m2 = fmaxf(m2, tmp[k]);
            float sum = 0.0f;
            #pragma unroll
            for (int k = 0; k < K2; ++k) { tmp[k] = __expf(tmp[k] - m2); sum += tmp[k]; }
            const float inv = 1.0f / sum;
            #pragma unroll
            for (int k = 0; k < K2; ++k) sc[k] = tmp[k] * inv;
        }
        for (int ch = 0; ch < DYN; ++ch) {
            const float* cp = xb + ch * HW;
            float acc = 0.0f;
            #pragma unroll
            for (int i = 0; i < KS; ++i) {
                const int gr = R - 2 + i;
                const float4 rv = ((unsigned)gr < NH) ? *(const float4*)(cp + gr * NW)
                                                      : make_float4(0.f, 0.f, 0.f, 0.f);
                if (col == 0) {
                    acc = fmaf(sc[i * KS + 2], rv.x, acc);
                    acc = fmaf(sc[i * KS + 3], rv.y, acc);
                    acc = fmaf(sc[i * KS + 4], rv.z, acc);
                } else {
                    acc = fmaf(sc[i * KS + 1], rv.x, acc);
                    acc = fmaf(sc[i * KS + 2], rv.y, acc);
                    acc = fmaf(sc[i * KS + 3], rv.z, acc);
                    acc = fmaf(sc[i * KS + 4], rv.w, acc);
                }
            }
            out[((long)(b * DYN + ch) * NH + R) * NW + col] = acc;
        }
        return;
    }

    // ===================== MAIN BLOCKS =====================
    extern __shared__ __align__(16) unsigned char dynsm[];
    float4* smbuf = (float4*)dynsm;                             // [BUFS][F4_CK]
    int*    sgoff = (int*)(dynsm + (size_t)BUFS * F4_CK * 16);  // [NSLOT][NTHR]
    float*  skw   = (float*)(sgoff + NSLOT * NTHR);             // [K2]

    const int tid = threadIdx.x;
    const int tx  = tid & 7;                  // 0..7
    const int ty  = tid >> 3;                 // 0..7
    const int w0  = blockIdx.x * TW;
    const int h0  = blockIdx.y * TH;
    const int b   = blockIdx.z;
    const int ph  = h0 + ty;
    const int p0  = w0 + 2 + tx * PW;         // first owned pixel (shifted by +2)

    // fold log2(e)/KS into tap weights -> exp2f softmax
    if (tid < K2) skw[tid] = kern[tid] * (1.4426950408889634f / KS);

    // ---- chunk-invariant fill descriptors; each thread reads only its own rows ----
    #pragma unroll
    for (int s = 0; s < NSLOT; ++s) {
        const int e   = tid + s * NTHR;
        const int ch  = e / F4_CH;
        const int rem = e - ch * F4_CH;
        const int r   = rem / (SW / 4);
        const int j   = rem - r * (SW / 4);
        const int gh  = h0 - 2 + r;
        const int gw0 = w0 + j * 4;
        const bool ok = (e < F4_CK) && ((unsigned)gh < NH) && ((unsigned)gw0 < NW);
        sgoff[s * NTHR + tid] = ok ? (ch * HW + gh * NW + gw0) : -1;
    }

    const float* xb = x + (long)b * NC * HW;

    // chunk -> channel base: 16 static chunks (c=32..63), then 16 dynamic (c=0..31)
    // ---- prologue: issue chunks 0..DIST-1 ----
    #pragma unroll
    for (int pre = 0; pre < DIST; ++pre) {
        const float* g = xb + (32 + CHK * pre) * HW;
        const uint32_t sb = (uint32_t)__cvta_generic_to_shared(&smbuf[(size_t)pre * F4_CK]);
        #pragma unroll
        for (int s = 0; s < NSLOT; ++s) {
            const int e = tid + s * NTHR;
            if (s < NSLOT - 1 || e < F4_CK) {
                const int off = sgoff[s * NTHR + tid];
                cp_async16(sb + (uint32_t)e * 16u, g + (off >= 0 ? off : 0),
                           off >= 0 ? 16u : 0u);
            }
        }
        cp_commit();
    }

    float sc[PW][K2];
    #pragma unroll
    for (int p = 0; p < PW; ++p)
        #pragma unroll
        for (int k = 0; k < K2; ++k) sc[p][k] = 0.0f;

    float inv[PW];

    for (int i = 0; i < NCHUNK; ++i) {
        // 1) issue chunk i+DIST into buffer (i+DIST)%BUFS BEFORE waiting.
        //    That buffer was last read at compute i+DIST-BUFS <= i-2, and every
        //    warp passed barrier i-1 after finishing compute i-2 => race-free.
        if (i + DIST < NCHUNK) {
            const int cn = i + DIST;
            const int cb = (cn < 16) ? (32 + CHK * cn) : (CHK * (cn - 16));
            const float* g = xb + cb * HW;
            const uint32_t sb = (uint32_t)__cvta_generic_to_shared(
                &smbuf[(size_t)(cn % BUFS) * F4_CK]);
            #pragma unroll
            for (int s = 0; s < NSLOT; ++s) {
                const int e = tid + s * NTHR;
                if (s < NSLOT - 1 || e < F4_CK) {
                    const int off = sgoff[s * NTHR + tid];
                    cp_async16(sb + (uint32_t)e * 16u, g + (off >= 0 ? off : 0),
                               off >= 0 ? 16u : 0u);
                }
            }
            cp_commit();
        }
        // 2) wait until chunk i complete (exact outstanding count at the tail)
        const int rem = NCHUNK - 1 - i;
        if      (rem >= DIST) { asm volatile("cp.async.wait_group 4;\n" ::: "memory"); }
        else if (rem == 3)    { asm volatile("cp.async.wait_group 3;\n" ::: "memory"); }
        else if (rem == 2)    { asm volatile("cp.async.wait_group 2;\n" ::: "memory"); }
        else if (rem == 1)    { asm volatile("cp.async.wait_group 1;\n" ::: "memory"); }
        else                  { asm volatile("cp.async.wait_group 0;\n" ::: "memory"); }
        // 3) barrier: chunk-i data visible to all; all warps done compute i-1
        __syncthreads();

        const float* buf = (const float*)&smbuf[(size_t)(i % BUFS) * F4_CK];

        if (i < 16) {
            // ================= Phase A: scores (scalar FFMA) =================
            #pragma unroll
            for (int cc = 0; cc < CHK; ++cc) {
                const float* chb = buf + cc * (SH * SW) + ty * SW + tx * 4;
                float v[PW];
                {   // row r=2: strip supplies taps AND the 4 center values
                    const float4 A = *(const float4*)(chb + 2 * SW);
                    const float4 B = *(const float4*)(chb + 2 * SW + 4);
                    v[0] = A.z; v[1] = A.w; v[2] = B.x; v[3] = B.y;
                    const float s[8] = {A.x, A.y, A.z, A.w, B.x, B.y, B.z, B.w};
                    #pragma unroll
                    for (int j = 0; j < KS; ++j)
                        #pragma unroll
                        for (int p = 0; p < PW; ++p)
                            sc[p][10 + j] = fmaf(s[j + p], v[p], sc[p][10 + j]);
                }
                #pragma unroll
                for (int rr = 0; rr < 4; ++rr) {
                    const int r = (rr < 2) ? rr : rr + 1;   // 0,1,3,4
                    const float4 A = *(const float4*)(chb + r * SW);
                    const float4 B = *(const float4*)(chb + r * SW + 4);
                    const float s[8] = {A.x, A.y, A.z, A.w, B.x, B.y, B.z, B.w};
                    #pragma unroll
                    for (int j = 0; j < KS; ++j)
                        #pragma unroll
                        for (int p = 0; p < PW; ++p)
                            sc[p][r * KS + j] = fmaf(s[j + p], v[p], sc[p][r * KS + j]);
                }
            }
            if (i == 15) {
                // ================= Phase B: softmax (log2 domain) =================
                #pragma unroll
                for (int k = 0; k < K2; ++k) {
                    const float kw = skw[k];
                    #pragma unroll
                    for (int p = 0; p < PW; ++p) sc[p][k] *= kw;
                }
                #pragma unroll
                for (int p = 0; p < PW; ++p) {
                    float mx = sc[p][0];
                    #pragma unroll
                    for (int k = 1; k < K2; ++k) mx = fmaxf(mx, sc[p][k]);
                    float sum = 0.0f;
                    #pragma unroll
                    for (int k = 0; k < K2; ++k) {
                        const float e = exp2f(sc[p][k] - mx);
                        sc[p][k] = e;
                        sum += e;
                    }
                    inv[p] = 1.0f / sum;
                }
            }
        } else {
            // ================= Phase C: weighted sum (scalar FFMA) =================
            #pragma unroll
            for (int cc = 0; cc < CHK; ++cc) {
                const float* chb = buf + cc * (SH * SW) + ty * SW + tx * 4;
                float acc[PW] = {0.f, 0.f, 0.f, 0.f};
                #pragma unroll
                for (int r = 0; r < KS; ++r) {
                    const float4 A = *(const float4*)(chb + r * SW);
                    const float4 B = *(const float4*)(chb + r * SW + 4);
                    const float s[8] = {A.x, A.y, A.z, A.w, B.x, B.y, B.z, B.w};
                    #pragma unroll
                    for (int j = 0; j < KS; ++j)
                        #pragma unroll
                        for (int p = 0; p < PW; ++p)
                            acc[p] = fmaf(sc[p][r * KS + j], s[j + p], acc[p]);
                }
                const int c = (i - 16) * CHK + cc;
                float* op = &out[(((long)b * DYN + c) * NH + ph) * NW + p0];
                float2 o0 = make_float2(acc[0] * inv[0], acc[1] * inv[1]);
                *(float2*)op = o0;                       // pixels p0, p0+1
                if (p0 + 2 < NW) {                        // masked for last block, tx=7
                    float2 o1 = make_float2(acc[2] * inv[2], acc[3] * inv[3]);
                    *(float2*)(op + 2) = o1;
                }
            }
        }
    }
}

extern "C" void kernel_launch(void* const* d_in, const int* in_sizes, int n_in,
                              void* d_out, int out_size)
{
    const float* x    = (const float*)d_in[0];
    const float* kern = (const float*)d_in[1];
    float* out        = (float*)d_out;
    (void)in_sizes; (void)n_in; (void)out_size;

    static bool attr_set = false;
    if (!attr_set) {
        cudaFuncSetAttribute(la_kernel, cudaFuncAttributeMaxDynamicSharedMemorySize,
                             SMEM_BYTES);
        attr_set = true;
    }

    dim3 grid(NW / TW, NH / TH + 1, NB);   // (8, 33, 4): by==32 -> edge blocks
    dim3 block(NTHR);
    la_kernel<<<grid, block, SMEM_BYTES>>>(x, kern, out);
}